// round 10
// baseline (speedup 1.0000x reference)
#include <cuda_runtime.h>
#include <cuda_fp16.h>
#include <cstdint>

#define HIDDEN 256
#define HEADS 8
#define MAXN 50000
#define MAXE 800000

// ---------------- scratch ----------------
// Permuted fp16 layout (per row of 256 halfs): half idx p in block n0=(p&128):
//   jl = p - n0; feat = n0 + (jl&1)*64 + (jl>>1)
// => word w: w<64 -> feats (w, w+64); w>=64 -> feats (w+64, w+128).
//   Both feats of a word share head (w%8); lane l reads words c*32+l -> head l%8.
__device__ __half g_qh[(size_t)MAXN * HIDDEN];
__device__ __half g_kh[(size_t)MAXN * HIDDEN];
__device__ __half g_vh[(size_t)MAXN * HIDDEN];
__device__ __half g_aoh[(size_t)MAXN * HIDDEN];
__device__ int    g_deg[MAXN];
__device__ int    g_offs[MAXN + 1];
__device__ int    g_cursor[MAXN];
__device__ int    g_ccol[MAXE];

// ---------------- CSR build ----------------
__global__ void count_deg_kernel(const int* __restrict__ row, int e) {
    int i = blockIdx.x * blockDim.x + threadIdx.x;
    if (i < e) atomicAdd(&g_deg[row[i]], 1);
}

__global__ void scan_kernel(int n) {
    __shared__ int wsum[32];
    int lane = threadIdx.x & 31;
    int wid  = threadIdx.x >> 5;
    int carry = 0;
    for (int base = 0; base < n; base += 1024) {
        int i = base + (int)threadIdx.x;
        int v = (i < n) ? g_deg[i] : 0;
        int x = v;
        #pragma unroll
        for (int d = 1; d < 32; d <<= 1) {
            int y = __shfl_up_sync(0xffffffffu, x, d);
            if (lane >= d) x += y;
        }
        if (lane == 31) wsum[wid] = x;
        __syncthreads();
        if (wid == 0) {
            int wv = wsum[lane];
            #pragma unroll
            for (int d = 1; d < 32; d <<= 1) {
                int y = __shfl_up_sync(0xffffffffu, wv, d);
                if (lane >= d) wv += y;
            }
            wsum[lane] = wv;
        }
        __syncthreads();
        int inc = x + (wid > 0 ? wsum[wid - 1] : 0) + carry;
        if (i < n) {
            int excl = inc - v;
            g_offs[i]   = excl;
            g_cursor[i] = excl;
        }
        carry += wsum[31];
        __syncthreads();
    }
    if (threadIdx.x == 0) g_offs[n] = carry;
}

__global__ void scatter_kernel(const int* __restrict__ row, const int* __restrict__ col, int e) {
    int i = blockIdx.x * blockDim.x + threadIdx.x;
    if (i < e) {
        int slot = atomicAdd(&g_cursor[row[i]], 1);
        g_ccol[slot] = col[i];
    }
}

// ================ shared GEMM pieces ================
#define ST_AH 0
#define ST_AL 4096
#define ST_BH 8192
#define ST_BL 12288
#define ST_SZ 16384

__device__ __forceinline__ uint32_t packh2(float x, float y) {
    __half2 h = __halves2half2(__float2half_rn(x), __float2half_rn(y));
    return *(uint32_t*)&h;
}
__device__ __forceinline__ uint32_t packlo2(float x, float y, uint32_t h) {
    __half2 hh = *(__half2*)&h;
    float rx = x - __half2float(__low2half(hh));
    float ry = y - __half2float(__high2half(hh));
    return packh2(rx, ry);
}

#define MMA_F16(ACC, AV, B0, B1)                                           \
    asm volatile(                                                          \
        "mma.sync.aligned.m16n8k16.row.col.f32.f16.f16.f32 "              \
        "{%0,%1,%2,%3}, {%4,%5,%6,%7}, {%8,%9}, {%0,%1,%2,%3};"           \
        : "+f"(ACC[0]), "+f"(ACC[1]), "+f"(ACC[2]), "+f"(ACC[3])          \
        : "r"(AV.x), "r"(AV.y), "r"(AV.z), "r"(AV.w),                     \
          "r"(B0), "r"(B1))

// ================ QKV GEMM: fp32 A, split A+B (3-term), fp16 permuted out ====
__global__ void __launch_bounds__(256, 2) gemm_qkv_kernel(
    const float* __restrict__ A,
    const float* __restrict__ W0, const float* __restrict__ W1, const float* __restrict__ W2,
    const float* __restrict__ b0_, const float* __restrict__ b1_, const float* __restrict__ b2_,
    __half* __restrict__ QH, __half* __restrict__ KH, __half* __restrict__ VH,
    int M, float scale0)
{
    __shared__ __align__(16) unsigned char sm[2][ST_SZ];

    const int z = blockIdx.z;
    const float* W    = (z == 0) ? W0 : (z == 1) ? W1 : W2;
    const float* bias = (z == 0) ? b0_ : (z == 1) ? b1_ : b2_;
    __half* H         = (z == 0) ? QH : (z == 1) ? KH : VH;
    const float scale = (z == 0) ? scale0 : 1.f;

    const int tid  = threadIdx.x;
    const int lane = tid & 31;
    const int warp = tid >> 5;
    const int g    = lane >> 2;
    const int tig  = lane & 3;
    const int wm   = (warp >> 1) * 32;
    const int wn   = (warp & 1) * 64;

    const int m0 = blockIdx.x * 128;
    const int n0 = blockIdx.y * 128;

    const int ftr = tid >> 5;
    const int fl  = lane;
    const int arow_lo = m0 + ftr * 16 + g;
    const int arow_hi = arow_lo + 8;
    const bool vlo = arow_lo < M, vhi = arow_hi < M;
    const float* Ap_ll = A + (size_t)arow_lo * HIDDEN + 2 * tig;
    const float* Ap_hl = A + (size_t)arow_hi * HIDDEN + 2 * tig;

    // permuted W rows so the fp16 epilogue is contiguous
    const int jl0 = ftr * 8 + g;
    const int jl1 = (ftr + 8) * 8 + g;
    const int wr0 = n0 + ((jl0 & 1) << 6) + (jl0 >> 1);
    const int wr1 = n0 + ((jl1 & 1) << 6) + (jl1 >> 1);
    const float* Wp0 = W + (size_t)wr0 * HIDDEN + 2 * tig;
    const float* Wp1 = W + (size_t)wr1 * HIDDEN + 2 * tig;

    float2 xa0, xa1, xa2, xa3, xb0, xb1, xb2, xb3;
    const float2 Z2 = make_float2(0.f, 0.f);

    xa0 = vlo ? *(const float2*)(Ap_ll)     : Z2;
    xa1 = vhi ? *(const float2*)(Ap_hl)     : Z2;
    xa2 = vlo ? *(const float2*)(Ap_ll + 8) : Z2;
    xa3 = vhi ? *(const float2*)(Ap_hl + 8) : Z2;
    xb0 = *(const float2*)(Wp0);
    xb1 = *(const float2*)(Wp0 + 8);
    xb2 = *(const float2*)(Wp1);
    xb3 = *(const float2*)(Wp1 + 8);

    float acc[2][8][4];
    #pragma unroll
    for (int mt = 0; mt < 2; mt++)
        #pragma unroll
        for (int nt = 0; nt < 8; nt++)
            #pragma unroll
            for (int r = 0; r < 4; r++) acc[mt][nt][r] = 0.f;

    {
        unsigned char* st = sm[0];
        uint4 h, l;
        h.x = packh2(xa0.x, xa0.y); l.x = packlo2(xa0.x, xa0.y, h.x);
        h.y = packh2(xa1.x, xa1.y); l.y = packlo2(xa1.x, xa1.y, h.y);
        h.z = packh2(xa2.x, xa2.y); l.z = packlo2(xa2.x, xa2.y, h.z);
        h.w = packh2(xa3.x, xa3.y); l.w = packlo2(xa3.x, xa3.y, h.w);
        *(uint4*)(st + ST_AH + ftr * 512 + fl * 16) = h;
        *(uint4*)(st + ST_AL + ftr * 512 + fl * 16) = l;
        uint2 bh0, bl0, bh1, bl1;
        bh0.x = packh2(xb0.x, xb0.y); bl0.x = packlo2(xb0.x, xb0.y, bh0.x);
        bh0.y = packh2(xb1.x, xb1.y); bl0.y = packlo2(xb1.x, xb1.y, bh0.y);
        bh1.x = packh2(xb2.x, xb2.y); bl1.x = packlo2(xb2.x, xb2.y, bh1.x);
        bh1.y = packh2(xb3.x, xb3.y); bl1.y = packlo2(xb3.x, xb3.y, bh1.y);
        *(uint2*)(st + ST_BH + ftr * 256 + fl * 8) = bh0;
        *(uint2*)(st + ST_BL + ftr * 256 + fl * 8) = bl0;
        *(uint2*)(st + ST_BH + (ftr + 8) * 256 + fl * 8) = bh1;
        *(uint2*)(st + ST_BL + (ftr + 8) * 256 + fl * 8) = bl1;
    }
    __syncthreads();

    #pragma unroll 1
    for (int it = 0; it < 16; it++) {
        if (it + 1 < 16) {
            int ko = (it + 1) * 16;
            xa0 = vlo ? *(const float2*)(Ap_ll + ko)     : Z2;
            xa1 = vhi ? *(const float2*)(Ap_hl + ko)     : Z2;
            xa2 = vlo ? *(const float2*)(Ap_ll + ko + 8) : Z2;
            xa3 = vhi ? *(const float2*)(Ap_hl + ko + 8) : Z2;
            xb0 = *(const float2*)(Wp0 + ko);
            xb1 = *(const float2*)(Wp0 + ko + 8);
            xb2 = *(const float2*)(Wp1 + ko);
            xb3 = *(const float2*)(Wp1 + ko + 8);
        }

        {
            const unsigned char* st = sm[it & 1];
            uint4 ah[2], al[2];
            #pragma unroll
            for (int mt = 0; mt < 2; mt++) {
                int tr = (wm >> 4) + mt;
                ah[mt] = *(const uint4*)(st + ST_AH + tr * 512 + lane * 16);
                al[mt] = *(const uint4*)(st + ST_AL + tr * 512 + lane * 16);
            }
            #pragma unroll
            for (int nt = 0; nt < 8; nt++) {
                int tn = (wn >> 3) + nt;
                uint2 bh = *(const uint2*)(st + ST_BH + tn * 256 + lane * 8);
                uint2 bl = *(const uint2*)(st + ST_BL + tn * 256 + lane * 8);
                // term-major: same-acc distance 2
                MMA_F16(acc[0][nt], al[0], bh.x, bh.y);
                MMA_F16(acc[1][nt], al[1], bh.x, bh.y);
                MMA_F16(acc[0][nt], ah[0], bl.x, bl.y);
                MMA_F16(acc[1][nt], ah[1], bl.x, bl.y);
                MMA_F16(acc[0][nt], ah[0], bh.x, bh.y);
                MMA_F16(acc[1][nt], ah[1], bh.x, bh.y);
            }
        }

        if (it + 1 < 16) {
            unsigned char* st = sm[(it + 1) & 1];
            uint4 h, l;
            h.x = packh2(xa0.x, xa0.y); l.x = packlo2(xa0.x, xa0.y, h.x);
            h.y = packh2(xa1.x, xa1.y); l.y = packlo2(xa1.x, xa1.y, h.y);
            h.z = packh2(xa2.x, xa2.y); l.z = packlo2(xa2.x, xa2.y, h.z);
            h.w = packh2(xa3.x, xa3.y); l.w = packlo2(xa3.x, xa3.y, h.w);
            *(uint4*)(st + ST_AH + ftr * 512 + fl * 16) = h;
            *(uint4*)(st + ST_AL + ftr * 512 + fl * 16) = l;
            uint2 bh0, bl0, bh1, bl1;
            bh0.x = packh2(xb0.x, xb0.y); bl0.x = packlo2(xb0.x, xb0.y, bh0.x);
            bh0.y = packh2(xb1.x, xb1.y); bl0.y = packlo2(xb1.x, xb1.y, bh0.y);
            bh1.x = packh2(xb2.x, xb2.y); bl1.x = packlo2(xb2.x, xb2.y, bh1.x);
            bh1.y = packh2(xb3.x, xb3.y); bl1.y = packlo2(xb3.x, xb3.y, bh1.y);
            *(uint2*)(st + ST_BH + ftr * 256 + fl * 8) = bh0;
            *(uint2*)(st + ST_BL + ftr * 256 + fl * 8) = bl0;
            *(uint2*)(st + ST_BH + (ftr + 8) * 256 + fl * 8) = bh1;
            *(uint2*)(st + ST_BL + (ftr + 8) * 256 + fl * 8) = bl1;
        }
        __syncthreads();
    }

    // fp16 permuted epilogue (all z)
    #pragma unroll
    for (int mt = 0; mt < 2; mt++) {
        int r0 = m0 + wm + mt * 16 + g;
        #pragma unroll
        for (int nt = 0; nt < 8; nt++) {
            int jl = wn + nt * 8 + 2 * tig;
            float bx = bias[n0 + (jl >> 1)];
            float by = bias[n0 + 64 + (jl >> 1)];
            if (r0 < M) {
                *(__half2*)(H + (size_t)r0 * HIDDEN + n0 + jl) =
                    __halves2half2(__float2half_rn((acc[mt][nt][0] + bx) * scale),
                                   __float2half_rn((acc[mt][nt][1] + by) * scale));
            }
            if (r0 + 8 < M) {
                *(__half2*)(H + (size_t)(r0 + 8) * HIDDEN + n0 + jl) =
                    __halves2half2(__float2half_rn((acc[mt][nt][2] + bx) * scale),
                                   __float2half_rn((acc[mt][nt][3] + by) * scale));
            }
        }
    }
}

// ================ O-proj GEMM: fp16 permuted A (exact), split B, 2-term ======
// A k-positions are permuted words; W columns fetched through the inverse perm:
//   word w -> cols (w + 64*[w>=64], +64)
__global__ void __launch_bounds__(256, 2) gemm_oproj_kernel(
    const __half* __restrict__ AH,
    const float* __restrict__ W, const float* __restrict__ bias,
    float* __restrict__ C, int M)
{
    __shared__ __align__(16) unsigned char sm[2][ST_SZ];

    const int tid  = threadIdx.x;
    const int lane = tid & 31;
    const int warp = tid >> 5;
    const int g    = lane >> 2;
    const int tig  = lane & 3;
    const int wm   = (warp >> 1) * 32;
    const int wn   = (warp & 1) * 64;

    const int m0 = blockIdx.x * 128;
    const int n0 = blockIdx.y * 128;

    const int ftr = tid >> 5;
    const int fl  = lane;
    const int arow_lo = m0 + ftr * 16 + g;
    const int arow_hi = arow_lo + 8;
    const bool vlo = arow_lo < M, vhi = arow_hi < M;
    const uint32_t* Aw_lo = (const uint32_t*)(AH + (size_t)arow_lo * HIDDEN);
    const uint32_t* Aw_hi = (const uint32_t*)(AH + (size_t)arow_hi * HIDDEN);

    const int wr0 = n0 + ftr * 8 + g;          // no row permutation (fp32 C out)
    const int wr1 = n0 + (ftr + 8) * 8 + g;
    const float* Wr0 = W + (size_t)wr0 * HIDDEN;
    const float* Wr1 = W + (size_t)wr1 * HIDDEN;

    uint32_t xa0, xa1, xa2, xa3;
    float2 xb0, xb1, xb2, xb3;

    // helper: load W pair for word w
    #define WPAIR(Wr, w) make_float2(Wr[(w) + (((w) >= 64) ? 64 : 0)],           \
                                     Wr[(w) + (((w) >= 64) ? 64 : 0) + 64])

    {
        int w0 = tig, w1 = tig + 4;
        xa0 = vlo ? Aw_lo[w0] : 0u;
        xa1 = vhi ? Aw_hi[w0] : 0u;
        xa2 = vlo ? Aw_lo[w1] : 0u;
        xa3 = vhi ? Aw_hi[w1] : 0u;
        xb0 = WPAIR(Wr0, w0); xb1 = WPAIR(Wr0, w1);
        xb2 = WPAIR(Wr1, w0); xb3 = WPAIR(Wr1, w1);
    }

    float acc[2][8][4];
    #pragma unroll
    for (int mt = 0; mt < 2; mt++)
        #pragma unroll
        for (int nt = 0; nt < 8; nt++)
            #pragma unroll
            for (int r = 0; r < 4; r++) acc[mt][nt][r] = 0.f;

    {
        unsigned char* st = sm[0];
        *(uint4*)(st + ST_AH + ftr * 512 + fl * 16) = make_uint4(xa0, xa1, xa2, xa3);
        uint2 bh0, bl0, bh1, bl1;
        bh0.x = packh2(xb0.x, xb0.y); bl0.x = packlo2(xb0.x, xb0.y, bh0.x);
        bh0.y = packh2(xb1.x, xb1.y); bl0.y = packlo2(xb1.x, xb1.y, bh0.y);
        bh1.x = packh2(xb2.x, xb2.y); bl1.x = packlo2(xb2.x, xb2.y, bh1.x);
        bh1.y = packh2(xb3.x, xb3.y); bl1.y = packlo2(xb3.x, xb3.y, bh1.y);
        *(uint2*)(st + ST_BH + ftr * 256 + fl * 8) = bh0;
        *(uint2*)(st + ST_BL + ftr * 256 + fl * 8) = bl0;
        *(uint2*)(st + ST_BH + (ftr + 8) * 256 + fl * 8) = bh1;
        *(uint2*)(st + ST_BL + (ftr + 8) * 256 + fl * 8) = bl1;
    }
    __syncthreads();

    #pragma unroll 1
    for (int it = 0; it < 16; it++) {
        if (it + 1 < 16) {
            int w0 = (it + 1) * 8 + tig, w1 = w0 + 4;
            xa0 = vlo ? Aw_lo[w0] : 0u;
            xa1 = vhi ? Aw_hi[w0] : 0u;
            xa2 = vlo ? Aw_lo[w1] : 0u;
            xa3 = vhi ? Aw_hi[w1] : 0u;
            xb0 = WPAIR(Wr0, w0); xb1 = WPAIR(Wr0, w1);
            xb2 = WPAIR(Wr1, w0); xb3 = WPAIR(Wr1, w1);
        }

        {
            const unsigned char* st = sm[it & 1];
            uint4 ah[2];
            #pragma unroll
            for (int mt = 0; mt < 2; mt++) {
                int tr = (wm >> 4) + mt;
                ah[mt] = *(const uint4*)(st + ST_AH + tr * 512 + lane * 16);
            }
            #pragma unroll
            for (int nt = 0; nt < 8; nt++) {
                int tn = (wn >> 3) + nt;
                uint2 bh = *(const uint2*)(st + ST_BH + tn * 256 + lane * 8);
                uint2 bl = *(const uint2*)(st + ST_BL + tn * 256 + lane * 8);
                MMA_F16(acc[0][nt], ah[0], bl.x, bl.y);
                MMA_F16(acc[1][nt], ah[1], bl.x, bl.y);
                MMA_F16(acc[0][nt], ah[0], bh.x, bh.y);
                MMA_F16(acc[1][nt], ah[1], bh.x, bh.y);
            }
        }

        if (it + 1 < 16) {
            unsigned char* st = sm[(it + 1) & 1];
            *(uint4*)(st + ST_AH + ftr * 512 + fl * 16) = make_uint4(xa0, xa1, xa2, xa3);
            uint2 bh0, bl0, bh1, bl1;
            bh0.x = packh2(xb0.x, xb0.y); bl0.x = packlo2(xb0.x, xb0.y, bh0.x);
            bh0.y = packh2(xb1.x, xb1.y); bl0.y = packlo2(xb1.x, xb1.y, bh0.y);
            bh1.x = packh2(xb2.x, xb2.y); bl1.x = packlo2(xb2.x, xb2.y, bh1.x);
            bh1.y = packh2(xb3.x, xb3.y); bl1.y = packlo2(xb3.x, xb3.y, bh1.y);
            *(uint2*)(st + ST_BH + ftr * 256 + fl * 8) = bh0;
            *(uint2*)(st + ST_BL + ftr * 256 + fl * 8) = bl0;
            *(uint2*)(st + ST_BH + (ftr + 8) * 256 + fl * 8) = bh1;
            *(uint2*)(st + ST_BL + (ftr + 8) * 256 + fl * 8) = bl1;
        }
        __syncthreads();
    }
    #undef WPAIR

    // fp32 epilogue
    #pragma unroll
    for (int mt = 0; mt < 2; mt++) {
        int r0 = m0 + wm + mt * 16 + g;
        #pragma unroll
        for (int nt = 0; nt < 8; nt++) {
            int c = n0 + wn + nt * 8 + 2 * tig;
            float bx = bias[c], by = bias[c + 1];
            if (r0 < M) {
                float2 o0;
                o0.x = acc[mt][nt][0] + bx;
                o0.y = acc[mt][nt][1] + by;
                *(float2*)(C + (size_t)r0 * HIDDEN + c) = o0;
            }
            if (r0 + 8 < M) {
                float2 o1;
                o1.x = acc[mt][nt][2] + bx;
                o1.y = acc[mt][nt][3] + by;
                *(float2*)(C + (size_t)(r0 + 8) * HIDDEN + c) = o1;
            }
        }
    }
}

// ---------------- attention: one warp per node, all-fp16, 8-edge unroll -----
__global__ void __launch_bounds__(256) attn_kernel(int n) {
    int gw   = (blockIdx.x * blockDim.x + threadIdx.x) >> 5;
    int lane = threadIdx.x & 31;
    if (gw >= n) return;
    const int i = gw;
    const int start = g_offs[i];
    const int end   = g_offs[i + 1];

    const __half2* QB = (const __half2*)g_qh;
    const __half2* KB = (const __half2*)g_kh;
    const __half2* VB = (const __half2*)g_vh;

    float2 ql[4];
    #pragma unroll
    for (int c = 0; c < 4; c++)
        ql[c] = __half22float2(QB[(size_t)i * 128 + c * 32 + lane]);

    float m = __int_as_float(0xff800000);
    float d = 0.f;
    float2 acc[4] = {};

    int p = start;
    for (; p + 7 < end; p += 8) {
        int cn[8];
        #pragma unroll
        for (int e = 0; e < 8; e++) cn[e] = g_ccol[p + e];

        float s[8] = {0.f, 0.f, 0.f, 0.f, 0.f, 0.f, 0.f, 0.f};
        #pragma unroll
        for (int c = 0; c < 4; c++) {
            int o = c * 32 + lane;
            #pragma unroll
            for (int e = 0; e < 8; e++) {
                float2 kf = __half22float2(__ldg(KB + (size_t)cn[e] * 128 + o));
                s[e] += ql[c].x * kf.x + ql[c].y * kf.y;
            }
        }
        #pragma unroll
        for (int e = 0; e < 8; e++) {
            s[e] += __shfl_xor_sync(0xffffffffu, s[e], 16);
            s[e] += __shfl_xor_sync(0xffffffffu, s[e], 8);
        }

        float m2 = m;
        #pragma unroll
        for (int e = 0; e < 8; e++) m2 = fmaxf(m2, s[e]);
        float cf = __expf(m - m2);
        float w[8], sw = 0.f;
        #pragma unroll
        for (int e = 0; e < 8; e++) { w[e] = __expf(s[e] - m2); sw += w[e]; }
        d = d * cf + sw;
        m = m2;

        #pragma unroll
        for (int c = 0; c < 4; c++) {
            int o = c * 32 + lane;
            float tx = acc[c].x * cf, ty = acc[c].y * cf;
            #pragma unroll
            for (int e = 0; e < 8; e++) {
                float2 vf = __half22float2(__ldg(VB + (size_t)cn[e] * 128 + o));
                tx += w[e] * vf.x;
                ty += w[e] * vf.y;
            }
            acc[c].x = tx; acc[c].y = ty;
        }
    }
    for (; p < end; p++) {
        int c0 = g_ccol[p];
        float s0 = 0.f;
        #pragma unroll
        for (int c = 0; c < 4; c++) {
            float2 kf = __half22float2(__ldg(KB + (size_t)c0 * 128 + c * 32 + lane));
            s0 += ql[c].x * kf.x + ql[c].y * kf.y;
        }
        s0 += __shfl_xor_sync(0xffffffffu, s0, 16);
        s0 += __shfl_xor_sync(0xffffffffu, s0, 8);
        float m2 = fmaxf(m, s0);
        float cf = __expf(m - m2);
        float w0 = __expf(s0 - m2);
        d = d * cf + w0;
        m = m2;
        #pragma unroll
        for (int c = 0; c < 4; c++) {
            float2 vf = __half22float2(__ldg(VB + (size_t)c0 * 128 + c * 32 + lane));
            acc[c].x = acc[c].x * cf + w0 * vf.x;
            acc[c].y = acc[c].y * cf + w0 * vf.y;
        }
    }

    float rd = (end > start) ? 1.f / d : 0.f;
    __half2* AO = (__half2*)g_aoh;
    #pragma unroll
    for (int c = 0; c < 4; c++) {
        AO[(size_t)i * 128 + c * 32 + lane] =
            __halves2half2(__float2half_rn(acc[c].x * rd),
                           __float2half_rn(acc[c].y * rd));
    }
}

// ---------------- launch ----------------
extern "C" void kernel_launch(void* const* d_in, const int* in_sizes, int n_in,
                              void* d_out, int out_size) {
    const float* h   = (const float*)d_in[0];
    const int*   row = (const int*)d_in[1];
    const int*   col = (const int*)d_in[2];
    const float* Wq  = (const float*)d_in[3];
    const float* bq  = (const float*)d_in[4];
    const float* Wk  = (const float*)d_in[5];
    const float* bk  = (const float*)d_in[6];
    const float* Wv  = (const float*)d_in[7];
    const float* bv  = (const float*)d_in[8];
    const float* Wo  = (const float*)d_in[9];
    const float* bo  = (const float*)d_in[10];
    float* out = (float*)d_out;

    const int N = in_sizes[0] / HIDDEN;
    const int E = in_sizes[1];

    __half *pqh, *pkh, *pvh, *paoh;
    int *pdeg;
    cudaGetSymbolAddress((void**)&pqh, g_qh);
    cudaGetSymbolAddress((void**)&pkh, g_kh);
    cudaGetSymbolAddress((void**)&pvh, g_vh);
    cudaGetSymbolAddress((void**)&paoh, g_aoh);
    cudaGetSymbolAddress((void**)&pdeg, g_deg);

    static cudaStream_t s2 = nullptr;
    static cudaEvent_t evFork = nullptr, evJoin = nullptr;
    if (!s2) {
        cudaStreamCreateWithFlags(&s2, cudaStreamNonBlocking);
        cudaEventCreateWithFlags(&evFork, cudaEventDisableTiming);
        cudaEventCreateWithFlags(&evJoin, cudaEventDisableTiming);
    }

    // fork: CSR build on s2, QKV GEMM on main stream
    cudaEventRecord(evFork, 0);
    cudaStreamWaitEvent(s2, evFork, 0);
    cudaMemsetAsync(pdeg, 0, (size_t)N * sizeof(int), s2);
    count_deg_kernel<<<(E + 255) / 256, 256, 0, s2>>>(row, E);
    scan_kernel<<<1, 1024, 0, s2>>>(N);
    scatter_kernel<<<(E + 255) / 256, 256, 0, s2>>>(row, col, E);
    cudaEventRecord(evJoin, s2);

    const float scaling = 0.17677669529663687f;  // 32^-0.5
    dim3 gqkv((N + 127) / 128, HIDDEN / 128, 3);
    gemm_qkv_kernel<<<gqkv, 256>>>(h, Wq, Wk, Wv, bq, bk, bv,
                                   pqh, pkh, pvh, N, scaling);

    cudaStreamWaitEvent(0, evJoin, 0);
    attn_kernel<<<(N + 7) / 8, 256>>>(N);

    dim3 go((N + 127) / 128, HIDDEN / 128, 1);
    gemm_oproj_kernel<<<go, 256>>>(paoh, Wo, bo, out, N);
}